// round 1
// baseline (speedup 1.0000x reference)
#include <cuda_runtime.h>

// Pure HBM-streaming quadratic form:
//   total = sum over pairs (l1<=l2), weight w in {1,2}:
//           w * sum_s d1[s,:] · O[s,:,:] · d2[s,:]
// Overlap tensors: 356.5 MB read once -> memory-bound. Everything else is tiny.

#define TPB 256
#define IT  8   // float4 per thread; all pair sizes divide evenly by TPB*IT

// delta coefficients, concatenated by l:
//   l0: [0,2048), l1: [2048,8192), l2: [8192,18432), l3: [18432,32768)
__device__ __align__(16) float g_d[32768];

__global__ void prep_kernel(const float* __restrict__ i0, const float* __restrict__ t0,
                            const float* __restrict__ i1, const float* __restrict__ t1,
                            const float* __restrict__ i2, const float* __restrict__ t2,
                            const float* __restrict__ i3, const float* __restrict__ t3,
                            float* out) {
    int idx = blockIdx.x * blockDim.x + threadIdx.x;
    if (idx == 0) out[0] = 0.0f;
    if (idx < 2048) {
        g_d[idx] = i0[idx] - t0[idx];
    } else if (idx < 8192) {
        int j = idx - 2048;  g_d[idx] = i1[j] - t1[j];
    } else if (idx < 18432) {
        int j = idx - 8192;  g_d[idx] = i2[j] - t2[j];
    } else if (idx < 32768) {
        int j = idx - 18432; g_d[idx] = i3[j] - t3[j];
    }
}

struct OvlpPtrs { const float4* p[10]; };

// Per-pair streaming accumulate. D1/D2 compile-time -> div/mod become mul-shift.
// lb = local block index within this pair's block range.
template <int D1, int D2, int W, int OFF1, int OFF2>
__device__ __forceinline__ float pair_acc(const float4* __restrict__ o, int lb, int tid) {
    constexpr unsigned C4 = D2 / 4;  // float4 columns; >= 64 so a warp shares one row r
    float acc = 0.0f;
    unsigned base = (unsigned)lb * (TPB * IT) + tid;
#pragma unroll
    for (int it = 0; it < IT; ++it) {
        unsigned idx4 = base + (unsigned)it * TPB;
        unsigned c4 = idx4 % C4;
        unsigned rs = idx4 / C4;
        unsigned r  = rs % (unsigned)D1;
        unsigned s  = rs / (unsigned)D1;
        float4 ov = __ldcs(&o[idx4]);                                   // streamed, evict-first
        const float4 d2 = *(const float4*)&g_d[OFF2 + s * D2 + c4 * 4]; // L1-resident
        float d1 = g_d[OFF1 + s * D1 + r] * (float)W;                   // warp-uniform broadcast
        acc = fmaf(d1, ov.x * d2.x + ov.y * d2.y + ov.z * d2.z + ov.w * d2.w, acc);
    }
    return acc;
}

// Block-count prefix sums per pair (each block = TPB*IT float4 = 8192 floats):
// (0,0):64  (0,1):192  (0,2):320  (0,3):448  (1,1):576
// (1,2):960 (1,3):1344 (2,2):1600 (2,3):2240 (3,3):3136   total = 10880
__global__ void __launch_bounds__(TPB) rho_kernel(OvlpPtrs o, float* __restrict__ out) {
    int b = blockIdx.x;
    int tid = threadIdx.x;
    float acc;
    if      (b <    64) acc = pair_acc< 256,  256, 1,     0,     0>(o.p[0], b,         tid);
    else if (b <   256) acc = pair_acc< 256,  768, 2,     0,  2048>(o.p[1], b -    64, tid);
    else if (b <   576) acc = pair_acc< 256, 1280, 2,     0,  8192>(o.p[2], b -   256, tid);
    else if (b <  1024) acc = pair_acc< 256, 1792, 2,     0, 18432>(o.p[3], b -   576, tid);
    else if (b <  1600) acc = pair_acc< 768,  768, 1,  2048,  2048>(o.p[4], b -  1024, tid);
    else if (b <  2560) acc = pair_acc< 768, 1280, 2,  2048,  8192>(o.p[5], b -  1600, tid);
    else if (b <  3904) acc = pair_acc< 768, 1792, 2,  2048, 18432>(o.p[6], b -  2560, tid);
    else if (b <  5504) acc = pair_acc<1280, 1280, 1,  8192,  8192>(o.p[7], b -  3904, tid);
    else if (b <  7744) acc = pair_acc<1280, 1792, 2,  8192, 18432>(o.p[8], b -  5504, tid);
    else                acc = pair_acc<1792, 1792, 1, 18432, 18432>(o.p[9], b -  7744, tid);

    // warp reduce
#pragma unroll
    for (int off = 16; off > 0; off >>= 1)
        acc += __shfl_down_sync(0xffffffffu, acc, off);

    __shared__ float ws[TPB / 32];
    if ((tid & 31) == 0) ws[tid >> 5] = acc;
    __syncthreads();
    if (tid == 0) {
        float s = ws[0];
#pragma unroll
        for (int w = 1; w < TPB / 32; ++w) s += ws[w];
        atomicAdd(out, s);
    }
}

extern "C" void kernel_launch(void* const* d_in, const int* in_sizes, int n_in,
                              void* d_out, int out_size) {
    (void)in_sizes; (void)n_in; (void)out_size;
    const float* i0 = (const float*)d_in[0];
    const float* t0 = (const float*)d_in[1];
    const float* i1 = (const float*)d_in[2];
    const float* t1 = (const float*)d_in[3];
    const float* i2 = (const float*)d_in[4];
    const float* t2 = (const float*)d_in[5];
    const float* i3 = (const float*)d_in[6];
    const float* t3 = (const float*)d_in[7];

    OvlpPtrs o;
    for (int k = 0; k < 10; ++k) o.p[k] = (const float4*)d_in[8 + k];

    float* out = (float*)d_out;
    prep_kernel<<<128, TPB>>>(i0, t0, i1, t1, i2, t2, i3, t3, out);
    rho_kernel<<<10880, TPB>>>(o, out);
}